// round 12
// baseline (speedup 1.0000x reference)
#include <cuda_runtime.h>
#include <cuda_fp16.h>
#include <cstdint>
#include <math.h>

#define NEXP 8
#define NTOK 4096
#define DM   1024
#define DFF  4096
#define ROWS_CAP 9216
#define MAXT 72

// ---------------- device scratch (total ~124.1 MiB — MUST stay < 128 MiB arena) --------
// g_buf is a lifetime union: [pack .. GEMM1] holds nibble-packed w1 (32 MiB);
//                            [GEMM2 .. gather] holds y = coef*(act@W2) (36 MiB fp32).
__device__ __align__(128) unsigned char g_buf[(size_t)ROWS_CAP * DM * 4];   // 36 MiB
__device__ __half    g_act[(size_t)ROWS_CAP * DFF];                          // 72 MiB
__device__ uint32_t  g_w2p[(size_t)NEXP * DFF * (DM / 8)];                   // 16 MiB
__device__ int       g_rowtok[ROWS_CAP];
__device__ float     g_rowcoef[ROWS_CAP];
__device__ int       g_tok2row[NTOK * 2];
__device__ int       g_tile_expert[MAXT];
__device__ int       g_ntiles;

// ---------------- pack: 8 int32 codes -> 1 uint32 of nibbles ----------------
// nibble j = col 2j ; nibble j+4 = col 2j+1 -> (w>>4j)&0x000F000F = cols (2j,2j+1).
__device__ __forceinline__ uint32_t pack8(const int4* __restrict__ q, int i) {
    int4 a = q[2 * i], b = q[2 * i + 1];
    return (uint32_t)a.x | ((uint32_t)a.z << 4) | ((uint32_t)b.x << 8) | ((uint32_t)b.z << 12)
         | ((uint32_t)a.y << 16) | ((uint32_t)a.w << 20) | ((uint32_t)b.y << 24) | ((uint32_t)b.w << 28);
}
__global__ void pack1_kernel(const int4* __restrict__ q) {
    int i = blockIdx.x * 256 + threadIdx.x;
    ((uint32_t*)g_buf)[i] = pack8(q, i);
}
__global__ void pack2_kernel(const int4* __restrict__ q) {
    int i = blockIdx.x * 256 + threadIdx.x;
    g_w2p[i] = pack8(q, i);
}

// ---------------- routing ----------------
__global__ void __launch_bounds__(1024) routing_kernel(const float* __restrict__ gating) {
    __shared__ int cnt[NEXP], off[NEXP], cur[NEXP];
    __shared__ int nrows_s;
    int t = threadIdx.x;
    if (t < NEXP) { cnt[t] = 0; cur[t] = 0; }
    __syncthreads();
    int be0[4], be1[4]; float bc0[4], bc1[4];
#pragma unroll
    for (int i = 0; i < 4; i++) {
        int tok = t * 4 + i;
        float l[NEXP]; float m = -3e38f;
#pragma unroll
        for (int e = 0; e < NEXP; e++) { l[e] = gating[tok * NEXP + e]; m = fmaxf(m, l[e]); }
        int b0 = 0; float v0 = l[0];
#pragma unroll
        for (int e = 1; e < NEXP; e++) if (l[e] > v0) { v0 = l[e]; b0 = e; }
        int b1 = -1; float v1 = -3e38f;
#pragma unroll
        for (int e = 0; e < NEXP; e++) if (e != b0 && l[e] > v1) { v1 = l[e]; b1 = e; }
        float p0 = __expf(v0 - m), p1 = __expf(v1 - m);
        float inv = 1.f / (p0 + p1);
        be0[i] = b0; bc0[i] = p0 * inv;
        be1[i] = b1; bc1[i] = p1 * inv;
        atomicAdd(&cnt[b0], 1); atomicAdd(&cnt[b1], 1);
    }
    __syncthreads();
    if (t == 0) {
        int o = 0;
        for (int e = 0; e < NEXP; e++) {
            off[e] = o;
            int p = (cnt[e] + 127) & ~127;
            for (int j = 0; j < (p >> 7); j++) g_tile_expert[(o >> 7) + j] = e;
            o += p;
        }
        g_ntiles = o >> 7;
        nrows_s = o;
    }
    __syncthreads();
    int nr = nrows_s;
    for (int r = t; r < nr; r += 1024) { g_rowtok[r] = 0; g_rowcoef[r] = 0.f; }
    __syncthreads();
#pragma unroll
    for (int i = 0; i < 4; i++) {
        int tok = t * 4 + i;
        int p0 = off[be0[i]] + atomicAdd(&cur[be0[i]], 1);
        g_rowtok[p0] = tok; g_rowcoef[p0] = bc0[i];
        g_tok2row[tok * 2 + 0] = p0;
        int p1 = off[be1[i]] + atomicAdd(&cur[be1[i]], 1);
        g_rowtok[p1] = tok; g_rowcoef[p1] = bc1[i];
        g_tok2row[tok * 2 + 1] = p1;
    }
}

// ---------------- warp primitives ----------------
__device__ __forceinline__ void mma16816(float* c, const uint32_t* a, const uint32_t* b) {
    asm volatile(
        "mma.sync.aligned.m16n8k16.row.col.f32.f16.f16.f32 "
        "{%0,%1,%2,%3}, {%4,%5,%6,%7}, {%8,%9}, {%0,%1,%2,%3};\n"
        : "+f"(c[0]), "+f"(c[1]), "+f"(c[2]), "+f"(c[3])
        : "r"(a[0]), "r"(a[1]), "r"(a[2]), "r"(a[3]), "r"(b[0]), "r"(b[1]));
}
__device__ __forceinline__ void ldsm4(uint32_t* r, uint32_t a) {
    asm volatile("ldmatrix.sync.aligned.m8n8.x4.shared.b16 {%0,%1,%2,%3}, [%4];"
        : "=r"(r[0]), "=r"(r[1]), "=r"(r[2]), "=r"(r[3]) : "r"(a));
}
__device__ __forceinline__ void ldsm4t(uint32_t* r, uint32_t a) {
    asm volatile("ldmatrix.sync.aligned.m8n8.x4.trans.shared.b16 {%0,%1,%2,%3}, [%4];"
        : "=r"(r[0]), "=r"(r[1]), "=r"(r[2]), "=r"(r[3]) : "r"(a));
}
__device__ __forceinline__ uint32_t smem_u32(const void* p) {
    uint32_t a;
    asm("{ .reg .u64 t; cvta.to.shared.u64 t, %1; cvt.u32.u64 %0, t; }" : "=r"(a) : "l"(p));
    return a;
}

// nibble word + 2 float4 scales -> one STS.128 of 8 dequantized fp16 weights
__device__ __forceinline__ void dqsts(uint32_t w, float4 sa, float4 sb, uint32_t addr) {
    const __half2 b8 = __half2half2(__ushort_as_half((unsigned short)0x6408));  // 1032.0
    __half2 s2[4];
    s2[0] = __floats2half2_rn(sa.x, sa.y); s2[1] = __floats2half2_rn(sa.z, sa.w);
    s2[2] = __floats2half2_rn(sb.x, sb.y); s2[3] = __floats2half2_rn(sb.z, sb.w);
    uint32_t o[4];
#pragma unroll
    for (int i = 0; i < 4; i++) {
        uint32_t p = ((w >> (4 * i)) & 0x000F000Fu) | 0x64006400u;
        __half2 v = __hsub2(*(__half2*)&p, b8);
        v = __hmul2(v, s2[i]);
        o[i] = *(uint32_t*)&v;
    }
    asm volatile("st.shared.v4.b32 [%0], {%1,%2,%3,%4};"
        :: "r"(addr), "r"(o[0]), "r"(o[1]), "r"(o[2]), "r"(o[3]) : "memory");
}

// ============ GEMM: CTA 128x128, K-chunk 32, 2-stage (R4-passing structure) ============
// A smem [128][40] halves; B smem k-major [32][136] halves (packed-nibble dequant).
// G1: A = x (fp32, converted on store). G2: A = g_act (fp16).
template<bool G1>
__global__ void __launch_bounds__(256, 1) gemm_hp(const float* __restrict__ xsrc,
                                                  const float* __restrict__ ws) {
    constexpr int KTOT = G1 ? DM : DFF;
    constexpr int NW   = G1 ? 2 * DFF : DM;     // gmem row width in cols
    constexpr int NWW  = NW / 8;                // gmem row width in packed words
    constexpr int NC   = KTOT / 32;

    int mt, nb;
    if (G1) {  // 8 groups of 8 nb; nb fastest within group (L2 reuse of A rows + weights)
        int idx = blockIdx.x;
        int grp = idx / (MAXT * 8);
        int wi  = idx - grp * (MAXT * 8);
        mt = wi >> 3; nb = grp * 8 + (wi & 7);
    } else { mt = blockIdx.y; nb = blockIdx.x; }
    if (mt >= g_ntiles) return;
    const int e    = g_tile_expert[mt];
    const int row0 = mt << 7;
    const int f0   = G1 ? nb * 64 : nb * 128;

    __shared__ __align__(16) __half sA[2][128 * 40];
    __shared__ __align__(16) __half sB[2][32 * 136];
    __shared__ int   sTok[128];
    __shared__ float sCoef[128];

    const int tid = threadIdx.x, lane = tid & 31, warp = tid >> 5;
    if (tid < 128) { sTok[tid] = g_rowtok[row0 + tid]; sCoef[tid] = g_rowcoef[row0 + tid]; }
    __syncthreads();

    // ---- B staging: lane-groups of 8 share k-row (conflict-free STS.128) ----
    const int bk = tid >> 3;                    // k-row 0..31
    const int w8 = tid & 7;                     // word within row
    constexpr int WDIFF = G1 ? (DFF / 8) : 8;   // region1 word offset
    constexpr int SDIFF = G1 ? DFF : 64;        // region1 scale-col offset
    const uint32_t* wpb = G1 ? (const uint32_t*)g_buf : g_w2p;
    const uint32_t* wp0 = wpb + (size_t)e * KTOT * NWW + (size_t)bk * NWW + (f0 >> 3) + w8;
    const float*    ws0 = ws + (size_t)e * (KTOT / 128) * NW + f0 + w8 * 8;
    const uint32_t  sm0 = (uint32_t)(bk * 136 + w8 * 8);   // halves

    // ---- A staging ----
    const int arow = tid >> 1, aseg = tid & 1;
    const float*  aF   = G1 ? (xsrc + (size_t)sTok[arow] * DM) : (const float*)0;
    const __half* aH   = G1 ? (const __half*)0 : (g_act + (size_t)(row0 + arow) * DFF);

    // ---- compute mapping (identical to passing kernel) ----
    const int wm = warp & 1, wn = warp >> 1;
    const int qr = lane >> 2, qc = (lane & 3) << 1;
    const int lrow = (lane & 7) + (((lane >> 3) & 1) << 3);
    const int lcol = (lane >> 4) << 3;
    const int n0_0 = G1 ? wn * 16      : wn * 32;
    const int n0_1 = G1 ? wn * 16 + 64 : wn * 32 + 16;

    float acc[4][4][4];
#pragma unroll
    for (int a = 0; a < 4; a++)
#pragma unroll
        for (int b = 0; b < 4; b++)
#pragma unroll
            for (int k = 0; k < 4; k++) acc[a][b][k] = 0.f;

    uint4  stA0, stA1;   // G2 staging
    float4 fA[4];        // G1 staging (fp32 x)
    uint32_t wr0, wr1;

    auto LOAD = [&](int c) {
        if (G1) {
            const float4* ap = (const float4*)(aF + c * 32 + aseg * 16);
            fA[0] = ap[0]; fA[1] = ap[1]; fA[2] = ap[2]; fA[3] = ap[3];
        } else {
            const uint4* ap = (const uint4*)(aH + c * 32 + aseg * 16);
            stA0 = ap[0]; stA1 = ap[1];
        }
        const uint32_t* q = wp0 + (size_t)(c * 32) * NWW;
        wr0 = q[0];
        wr1 = q[WDIFF];
    };
    auto STORE = [&](int cc, int s) {
        uint32_t* d = (uint32_t*)&sA[s][arow * 40 + aseg * 16];
        if (G1) {
#pragma unroll
            for (int j = 0; j < 4; j++) {
                __half2 lo = __floats2half2_rn(fA[j].x, fA[j].y);
                __half2 hi = __floats2half2_rn(fA[j].z, fA[j].w);
                d[2 * j]     = *(uint32_t*)&lo;
                d[2 * j + 1] = *(uint32_t*)&hi;
            }
        } else {
            d[0] = stA0.x; d[1] = stA0.y; d[2] = stA0.z; d[3] = stA0.w;
            d[4] = stA1.x; d[5] = stA1.y; d[6] = stA1.z; d[7] = stA1.w;
        }
        const float* p0 = ws0 + (size_t)(cc >> 2) * NW;   // scale group = 4 chunks
        const uint32_t base = smem_u32(&sB[s][0]);
        dqsts(wr0, *(const float4*)p0, *(const float4*)(p0 + 4), base + sm0 * 2);
        dqsts(wr1, *(const float4*)(p0 + SDIFF), *(const float4*)(p0 + SDIFF + 4),
              base + (sm0 + 64) * 2);
    };
    auto MMAS = [&](int s) {
        uint32_t aB = smem_u32(&sA[s][0]) + (uint32_t)(((wm * 64 + lrow) * 40 + lcol) * 2);
        uint32_t bB = smem_u32(&sB[s][0]) + (uint32_t)((lrow * 136 + lcol) * 2);
#pragma unroll
        for (int ks = 0; ks < 2; ks++) {
            uint32_t A[4][4], B0[4], B1[4];
#pragma unroll
            for (int mf = 0; mf < 4; mf++) ldsm4(A[mf], aB + mf * 1280 + ks * 32);
            ldsm4t(B0, bB + ks * 4352 + n0_0 * 2);
            ldsm4t(B1, bB + ks * 4352 + n0_1 * 2);
#pragma unroll
            for (int mf = 0; mf < 4; mf++) {
                mma16816(acc[mf][0], A[mf], &B0[0]);
                mma16816(acc[mf][1], A[mf], &B0[2]);
                mma16816(acc[mf][2], A[mf], &B1[0]);
                mma16816(acc[mf][3], A[mf], &B1[2]);
            }
        }
    };

    LOAD(0); STORE(0, 0); __syncthreads();
    for (int c = 0; c < NC; c++) {
        const int s = c & 1;
        if (c + 1 < NC) LOAD(c + 1);
        MMAS(s);
        if (c + 1 < NC) STORE(c + 1, s ^ 1);
        __syncthreads();
    }

    // ---- epilogue (identical to passing kernel; G2 writes y into g_buf union) ----
    if (G1) {
#pragma unroll
        for (int mf = 0; mf < 4; mf++)
#pragma unroll
            for (int t = 0; t < 2; t++)
#pragma unroll
                for (int h = 0; h < 2; h++) {
                    int r = row0 + wm * 64 + mf * 16 + qr + h * 8;
                    int f = f0 + wn * 16 + t * 8 + qc;
                    float g0 = acc[mf][t][h * 2 + 0], g1 = acc[mf][t][h * 2 + 1];
                    float u0 = acc[mf][t + 2][h * 2 + 0], u1 = acc[mf][t + 2][h * 2 + 1];
                    float a0 = g0 / (1.f + __expf(-g0)) * u0;
                    float a1 = g1 / (1.f + __expf(-g1)) * u1;
                    *(__half2*)(g_act + (size_t)r * DFF + f) = __floats2half2_rn(a0, a1);
                }
    } else {
        float* gy = (float*)g_buf;
#pragma unroll
        for (int mf = 0; mf < 4; mf++)
#pragma unroll
            for (int nf = 0; nf < 4; nf++)
#pragma unroll
                for (int h = 0; h < 2; h++) {
                    int rl = wm * 64 + mf * 16 + qr + h * 8;
                    float cf = sCoef[rl];
                    int col = f0 + wn * 32 + (nf >> 1) * 16 + (nf & 1) * 8 + qc;
                    *(float2*)(gy + (size_t)(row0 + rl) * DM + col) =
                        make_float2(cf * acc[mf][nf][h * 2 + 0], cf * acc[mf][nf][h * 2 + 1]);
                }
    }
}

// ---------------- gather: out[tok] = y[row0] + y[row1] ----------------
__global__ void gather_kernel(float4* __restrict__ out4) {
    int i = blockIdx.x * 256 + threadIdx.x;
    int t = i >> 8, c = i & 255;
    int r0 = g_tok2row[t * 2 + 0], r1 = g_tok2row[t * 2 + 1];
    const float* gy = (const float*)g_buf;
    float4 a = ((const float4*)(gy + (size_t)r0 * DM))[c];
    float4 b = ((const float4*)(gy + (size_t)r1 * DM))[c];
    out4[i] = make_float4(a.x + b.x, a.y + b.y, a.z + b.z, a.w + b.w);
}

// ---------------- launch ----------------
extern "C" void kernel_launch(void* const* d_in, const int* in_sizes, int n_in,
                              void* d_out, int out_size) {
    const float* x   = (const float*)d_in[0];
    const float* gt  = (const float*)d_in[1];
    const int*   w1q = (const int*)d_in[2];
    const int*   w2q = (const int*)d_in[3];
    const float* w1s = (const float*)d_in[4];
    const float* w2s = (const float*)d_in[5];

    routing_kernel<<<1, 1024>>>(gt);
    pack1_kernel<<<(NEXP * DM * 2 * DFF / 8) / 256, 256>>>((const int4*)w1q);
    pack2_kernel<<<(NEXP * DFF * DM / 8) / 256, 256>>>((const int4*)w2q);
    gemm_hp<true ><<<dim3(8 * MAXT * 8), 256>>>(x, w1s);
    gemm_hp<false><<<dim3(8, MAXT), 256>>>(x, w2s);
    gather_kernel<<<(NTOK * DM / 4) / 256, 256>>>((float4*)d_out);
}

// round 13
// speedup vs baseline: 1.3790x; 1.3790x over previous
#include <cuda_runtime.h>
#include <cuda_fp16.h>
#include <cstdint>
#include <math.h>

#define NEXP 8
#define NTOK 4096
#define DM   1024
#define DFF  4096
#define ROWS_CAP 9216
#define MAXT 72

// ---------------- device scratch (total ~124.1 MiB — MUST stay < 128 MiB arena) --------
// g_buf  union: [pack1 .. GEMM1] nibble-packed w1 (32 MiB) ; [GEMM2 .. gather] y fp32 (36 MiB)
// g_w2x  union: [prep .. GEMM1] x in fp16 (8 MiB) ; [pack2 .. GEMM2] nibble-packed w2 (16 MiB)
__device__ __align__(128) unsigned char g_buf[(size_t)ROWS_CAP * DM * 4];     // 36 MiB
__device__ __half    g_act[(size_t)ROWS_CAP * DFF];                            // 72 MiB
__device__ uint32_t  g_w2x[(size_t)NEXP * DFF * (DM / 8)];                     // 16 MiB
__device__ int       g_rowtok[ROWS_CAP];
__device__ float     g_rowcoef[ROWS_CAP];
__device__ int       g_tok2row[NTOK * 2];
__device__ int       g_tile_expert[MAXT];
__device__ int       g_ntiles;

// ---------------- prep: x -> fp16 (into g_w2x union, first 8 MiB) ----------------
__global__ void prep_kernel(const float4* __restrict__ x4) {
    int i = blockIdx.x * 256 + threadIdx.x;
    float4 v = x4[i];
    __half2 h0 = __floats2half2_rn(v.x, v.y);
    __half2 h1 = __floats2half2_rn(v.z, v.w);
    uint2 u;
    u.x = *(const uint32_t*)&h0;
    u.y = *(const uint32_t*)&h1;
    ((uint2*)g_w2x)[i] = u;
}

// ---------------- pack: 8 int32 codes -> 1 uint32 of nibbles ----------------
// nibble j = col 2j ; nibble j+4 = col 2j+1 -> (w>>4j)&0x000F000F = cols (2j,2j+1).
__device__ __forceinline__ uint32_t pack8(const int4* __restrict__ q, int i) {
    int4 a = q[2 * i], b = q[2 * i + 1];
    return (uint32_t)a.x | ((uint32_t)a.z << 4) | ((uint32_t)b.x << 8) | ((uint32_t)b.z << 12)
         | ((uint32_t)a.y << 16) | ((uint32_t)a.w << 20) | ((uint32_t)b.y << 24) | ((uint32_t)b.w << 28);
}
__global__ void pack1_kernel(const int4* __restrict__ q) {
    int i = blockIdx.x * 256 + threadIdx.x;
    ((uint32_t*)g_buf)[i] = pack8(q, i);
}
__global__ void pack2_kernel(const int4* __restrict__ q) {   // runs AFTER gemm1
    int i = blockIdx.x * 256 + threadIdx.x;
    g_w2x[i] = pack8(q, i);
}

// ---------------- routing ----------------
__global__ void __launch_bounds__(1024) routing_kernel(const float* __restrict__ gating) {
    __shared__ int cnt[NEXP], off[NEXP], cur[NEXP];
    __shared__ int nrows_s;
    int t = threadIdx.x;
    if (t < NEXP) { cnt[t] = 0; cur[t] = 0; }
    __syncthreads();
    int be0[4], be1[4]; float bc0[4], bc1[4];
#pragma unroll
    for (int i = 0; i < 4; i++) {
        int tok = t * 4 + i;
        float l[NEXP]; float m = -3e38f;
#pragma unroll
        for (int e = 0; e < NEXP; e++) { l[e] = gating[tok * NEXP + e]; m = fmaxf(m, l[e]); }
        int b0 = 0; float v0 = l[0];
#pragma unroll
        for (int e = 1; e < NEXP; e++) if (l[e] > v0) { v0 = l[e]; b0 = e; }
        int b1 = -1; float v1 = -3e38f;
#pragma unroll
        for (int e = 0; e < NEXP; e++) if (e != b0 && l[e] > v1) { v1 = l[e]; b1 = e; }
        float p0 = __expf(v0 - m), p1 = __expf(v1 - m);
        float inv = 1.f / (p0 + p1);
        be0[i] = b0; bc0[i] = p0 * inv;
        be1[i] = b1; bc1[i] = p1 * inv;
        atomicAdd(&cnt[b0], 1); atomicAdd(&cnt[b1], 1);
    }
    __syncthreads();
    if (t == 0) {
        int o = 0;
        for (int e = 0; e < NEXP; e++) {
            off[e] = o;
            int p = (cnt[e] + 127) & ~127;
            for (int j = 0; j < (p >> 7); j++) g_tile_expert[(o >> 7) + j] = e;
            o += p;
        }
        g_ntiles = o >> 7;
        nrows_s = o;
    }
    __syncthreads();
    int nr = nrows_s;
    for (int r = t; r < nr; r += 1024) { g_rowtok[r] = 0; g_rowcoef[r] = 0.f; }
    __syncthreads();
#pragma unroll
    for (int i = 0; i < 4; i++) {
        int tok = t * 4 + i;
        int p0 = off[be0[i]] + atomicAdd(&cur[be0[i]], 1);
        g_rowtok[p0] = tok; g_rowcoef[p0] = bc0[i];
        g_tok2row[tok * 2 + 0] = p0;
        int p1 = off[be1[i]] + atomicAdd(&cur[be1[i]], 1);
        g_rowtok[p1] = tok; g_rowcoef[p1] = bc1[i];
        g_tok2row[tok * 2 + 1] = p1;
    }
}

// ---------------- warp primitives ----------------
__device__ __forceinline__ void mma16816(float* c, const uint32_t* a, const uint32_t* b) {
    asm volatile(
        "mma.sync.aligned.m16n8k16.row.col.f32.f16.f16.f32 "
        "{%0,%1,%2,%3}, {%4,%5,%6,%7}, {%8,%9}, {%0,%1,%2,%3};\n"
        : "+f"(c[0]), "+f"(c[1]), "+f"(c[2]), "+f"(c[3])
        : "r"(a[0]), "r"(a[1]), "r"(a[2]), "r"(a[3]), "r"(b[0]), "r"(b[1]));
}
__device__ __forceinline__ void ldsm4(uint32_t* r, uint32_t a) {
    asm volatile("ldmatrix.sync.aligned.m8n8.x4.shared.b16 {%0,%1,%2,%3}, [%4];"
        : "=r"(r[0]), "=r"(r[1]), "=r"(r[2]), "=r"(r[3]) : "r"(a));
}
__device__ __forceinline__ void ldsm4t(uint32_t* r, uint32_t a) {
    asm volatile("ldmatrix.sync.aligned.m8n8.x4.trans.shared.b16 {%0,%1,%2,%3}, [%4];"
        : "=r"(r[0]), "=r"(r[1]), "=r"(r[2]), "=r"(r[3]) : "r"(a));
}
__device__ __forceinline__ uint32_t smem_u32(const void* p) {
    uint32_t a;
    asm("{ .reg .u64 t; cvta.to.shared.u64 t, %1; cvt.u32.u64 %0, t; }" : "=r"(a) : "l"(p));
    return a;
}

// nibble word + 2 float4 scales -> one STS.128 of 8 dequantized fp16 weights
__device__ __forceinline__ void dqsts(uint32_t w, float4 sa, float4 sb, uint32_t addr) {
    const __half2 b8 = __half2half2(__ushort_as_half((unsigned short)0x6408));  // 1032.0
    __half2 s2[4];
    s2[0] = __floats2half2_rn(sa.x, sa.y); s2[1] = __floats2half2_rn(sa.z, sa.w);
    s2[2] = __floats2half2_rn(sb.x, sb.y); s2[3] = __floats2half2_rn(sb.z, sb.w);
    uint32_t o[4];
#pragma unroll
    for (int i = 0; i < 4; i++) {
        uint32_t p = ((w >> (4 * i)) & 0x000F000Fu) | 0x64006400u;
        __half2 v = __hsub2(*(__half2*)&p, b8);
        v = __hmul2(v, s2[i]);
        o[i] = *(uint32_t*)&v;
    }
    asm volatile("st.shared.v4.b32 [%0], {%1,%2,%3,%4};"
        :: "r"(addr), "r"(o[0]), "r"(o[1]), "r"(o[2]), "r"(o[3]) : "memory");
}

// ============ GEMM: CTA 128x128, K-chunk 32, 2-stage, 2 CTAs/SM (R4 structure) ============
// A smem [128][40] halves (fp16 source both phases); B smem k-major [32][136] halves.
template<bool G1>
__global__ void __launch_bounds__(256, 2) gemm_hp(const float* __restrict__ ws) {
    constexpr int KTOT = G1 ? DM : DFF;
    constexpr int NW   = G1 ? 2 * DFF : DM;     // gmem row width in cols
    constexpr int NWW  = NW / 8;                // gmem row width in packed words
    constexpr int NC   = KTOT / 32;

    int mt, nb;
    if (G1) {  // 8 groups of 8 nb; nb fastest within group (L2 reuse of A-tiles + weights)
        int idx = blockIdx.x;
        int grp = idx / (MAXT * 8);
        int wi  = idx - grp * (MAXT * 8);
        mt = wi >> 3; nb = grp * 8 + (wi & 7);
    } else { mt = blockIdx.y; nb = blockIdx.x; }
    if (mt >= g_ntiles) return;
    const int e    = g_tile_expert[mt];
    const int row0 = mt << 7;
    const int f0   = G1 ? nb * 64 : nb * 128;

    __shared__ __align__(16) __half sA[2][128 * 40];
    __shared__ __align__(16) __half sB[2][32 * 136];
    __shared__ int   sTok[128];
    __shared__ float sCoef[128];

    const int tid = threadIdx.x, lane = tid & 31, warp = tid >> 5;
    if (tid < 128) { sTok[tid] = g_rowtok[row0 + tid]; sCoef[tid] = g_rowcoef[row0 + tid]; }
    __syncthreads();

    // ---- B staging: lane-groups of 8 share k-row (conflict-free STS.128) ----
    const int bk = tid >> 3;                    // k-row 0..31
    const int w8 = tid & 7;                     // word within row
    constexpr int WDIFF = G1 ? (DFF / 8) : 8;   // region1 word offset
    constexpr int SDIFF = G1 ? DFF : 64;        // region1 scale-col offset
    const uint32_t* wpb = G1 ? (const uint32_t*)g_buf : g_w2x;
    const uint32_t* wp0 = wpb + (size_t)e * KTOT * NWW + (size_t)bk * NWW + (f0 >> 3) + w8;
    const float*    ws0 = ws + (size_t)e * (KTOT / 128) * NW + f0 + w8 * 8;
    const uint32_t  sm0 = (uint32_t)(bk * 136 + w8 * 8);   // halves

    // ---- A staging (fp16 in both phases; G1 reads xh union) ----
    const int arow = tid >> 1, aseg = tid & 1;
    const __half* aSrc = G1 ? ((const __half*)g_w2x + (size_t)sTok[arow] * DM)
                            : (g_act + (size_t)(row0 + arow) * DFF);

    // ---- compute mapping (identical to R4-passing kernel) ----
    const int wm = warp & 1, wn = warp >> 1;
    const int qr = lane >> 2, qc = (lane & 3) << 1;
    const int lrow = (lane & 7) + (((lane >> 3) & 1) << 3);
    const int lcol = (lane >> 4) << 3;
    const int n0_0 = G1 ? wn * 16      : wn * 32;
    const int n0_1 = G1 ? wn * 16 + 64 : wn * 32 + 16;

    float acc[4][4][4];
#pragma unroll
    for (int a = 0; a < 4; a++)
#pragma unroll
        for (int b = 0; b < 4; b++)
#pragma unroll
            for (int k = 0; k < 4; k++) acc[a][b][k] = 0.f;

    uint4 stA0, stA1;
    uint32_t wr0, wr1;

    auto LOAD = [&](int c) {
        const uint4* ap = (const uint4*)(aSrc + c * 32 + aseg * 16);
        stA0 = ap[0]; stA1 = ap[1];
        const uint32_t* q = wp0 + (size_t)(c * 32) * NWW;
        wr0 = q[0];
        wr1 = q[WDIFF];
    };
    auto STORE = [&](int cc, int s) {
        uint32_t* d = (uint32_t*)&sA[s][arow * 40 + aseg * 16];
        d[0] = stA0.x; d[1] = stA0.y; d[2] = stA0.z; d[3] = stA0.w;
        d[4] = stA1.x; d[5] = stA1.y; d[6] = stA1.z; d[7] = stA1.w;
        const float* p0 = ws0 + (size_t)(cc >> 2) * NW;   // scale group = 4 chunks
        const uint32_t base = smem_u32(&sB[s][0]);
        dqsts(wr0, *(const float4*)p0, *(const float4*)(p0 + 4), base + sm0 * 2);
        dqsts(wr1, *(const float4*)(p0 + SDIFF), *(const float4*)(p0 + SDIFF + 4),
              base + (sm0 + 64) * 2);
    };
    auto MMAS = [&](int s) {
        uint32_t aB = smem_u32(&sA[s][0]) + (uint32_t)(((wm * 64 + lrow) * 40 + lcol) * 2);
        uint32_t bB = smem_u32(&sB[s][0]) + (uint32_t)((lrow * 136 + lcol) * 2);
#pragma unroll
        for (int ks = 0; ks < 2; ks++) {
            uint32_t A[4][4], B0[4], B1[4];
#pragma unroll
            for (int mf = 0; mf < 4; mf++) ldsm4(A[mf], aB + mf * 1280 + ks * 32);
            ldsm4t(B0, bB + ks * 4352 + n0_0 * 2);
            ldsm4t(B1, bB + ks * 4352 + n0_1 * 2);
#pragma unroll
            for (int mf = 0; mf < 4; mf++) {
                mma16816(acc[mf][0], A[mf], &B0[0]);
                mma16816(acc[mf][1], A[mf], &B0[2]);
                mma16816(acc[mf][2], A[mf], &B1[0]);
                mma16816(acc[mf][3], A[mf], &B1[2]);
            }
        }
    };

    LOAD(0); STORE(0, 0); __syncthreads();
    for (int c = 0; c < NC; c++) {
        const int s = c & 1;
        if (c + 1 < NC) LOAD(c + 1);
        MMAS(s);
        if (c + 1 < NC) STORE(c + 1, s ^ 1);
        __syncthreads();
    }

    // ---- epilogue (identical to R4-passing kernel; G2 writes y into g_buf union) ----
    if (G1) {
#pragma unroll
        for (int mf = 0; mf < 4; mf++)
#pragma unroll
            for (int t = 0; t < 2; t++)
#pragma unroll
                for (int h = 0; h < 2; h++) {
                    int r = row0 + wm * 64 + mf * 16 + qr + h * 8;
                    int f = f0 + wn * 16 + t * 8 + qc;
                    float g0 = acc[mf][t][h * 2 + 0], g1 = acc[mf][t][h * 2 + 1];
                    float u0 = acc[mf][t + 2][h * 2 + 0], u1 = acc[mf][t + 2][h * 2 + 1];
                    float a0 = g0 / (1.f + __expf(-g0)) * u0;
                    float a1 = g1 / (1.f + __expf(-g1)) * u1;
                    *(__half2*)(g_act + (size_t)r * DFF + f) = __floats2half2_rn(a0, a1);
                }
    } else {
        float* gy = (float*)g_buf;
#pragma unroll
        for (int mf = 0; mf < 4; mf++)
#pragma unroll
            for (int nf = 0; nf < 4; nf++)
#pragma unroll
                for (int h = 0; h < 2; h++) {
                    int rl = wm * 64 + mf * 16 + qr + h * 8;
                    float cf = sCoef[rl];
                    int col = f0 + wn * 32 + (nf >> 1) * 16 + (nf & 1) * 8 + qc;
                    *(float2*)(gy + (size_t)(row0 + rl) * DM + col) =
                        make_float2(cf * acc[mf][nf][h * 2 + 0], cf * acc[mf][nf][h * 2 + 1]);
                }
    }
}

// ---------------- gather: out[tok] = y[row0] + y[row1] ----------------
__global__ void gather_kernel(float4* __restrict__ out4) {
    int i = blockIdx.x * 256 + threadIdx.x;
    int t = i >> 8, c = i & 255;
    int r0 = g_tok2row[t * 2 + 0], r1 = g_tok2row[t * 2 + 1];
    const float* gy = (const float*)g_buf;
    float4 a = ((const float4*)(gy + (size_t)r0 * DM))[c];
    float4 b = ((const float4*)(gy + (size_t)r1 * DM))[c];
    out4[i] = make_float4(a.x + b.x, a.y + b.y, a.z + b.z, a.w + b.w);
}

// ---------------- launch ----------------
extern "C" void kernel_launch(void* const* d_in, const int* in_sizes, int n_in,
                              void* d_out, int out_size) {
    const float* x   = (const float*)d_in[0];
    const float* gt  = (const float*)d_in[1];
    const int*   w1q = (const int*)d_in[2];
    const int*   w2q = (const int*)d_in[3];
    const float* w1s = (const float*)d_in[4];
    const float* w2s = (const float*)d_in[5];

    prep_kernel<<<(NTOK * DM / 4) / 256, 256>>>((const float4*)x);
    routing_kernel<<<1, 1024>>>(gt);
    pack1_kernel<<<(NEXP * DM * 2 * DFF / 8) / 256, 256>>>((const int4*)w1q);
    gemm_hp<true ><<<dim3(8 * MAXT * 8), 256>>>(w1s);
    pack2_kernel<<<(NEXP * DFF * DM / 8) / 256, 256>>>((const int4*)w2q);   // after gemm1: reuses xh buffer
    gemm_hp<false><<<dim3(8, MAXT), 256>>>(w2s);
    gather_kernel<<<(NTOK * DM / 4) / 256, 256>>>((float4*)d_out);
}